// round 3
// baseline (speedup 1.0000x reference)
#include <cuda_runtime.h>
#include <cstdint>

// out[p] = (L >= 0) || (missing(p) - L >= 0.5), written as float 0.0/1.0
// L = 7-point Laplacian (6*center - face neighbors, zero padding);
// missing(p) = count of out-of-grid face neighbors (kernel sums to 0, so
// conv(1-m,k) = missing(p) - conv(m,k)).
//
// Each thread: one x-quad (float4) of one y-row, rolling over KZ z-slices.
// Center rows A/B/C roll in registers: 3 float4 + 2 scalar loads per z-step.

#define DSZ 192
#define KZ  12

__global__ __launch_bounds__(384) void mask_kernel(
    const float* __restrict__ m, float* __restrict__ out)
{
    const int tx = threadIdx.x;                       // 0..47 -> x quad
    const int y  = blockIdx.y * blockDim.y + threadIdx.y;
    const int zb = blockIdx.z;
    const int z0 = (zb & 15) * KZ;                    // 192/KZ = 16 z-tiles
    const int b  = zb >> 4;
    const int x0 = tx * 4;

    const size_t plane = (size_t)DSZ * DSZ;
    const float* p = m + (((size_t)b * DSZ + z0) * DSZ + y) * DSZ + x0;
    float* q = out + (((size_t)b * DSZ + z0) * DSZ + y) * DSZ + x0;

    const float4 zero4 = make_float4(0.f, 0.f, 0.f, 0.f);
    const bool hasYm = (y > 0);
    const bool hasYp = (y < DSZ - 1);
    const bool hasXl = (x0 > 0);
    const bool hasXr = (x0 + 4 < DSZ);
    const int  missY = (int)(!hasYm) + (int)(!hasYp);
    const float missE0 = (float)(missY + (int)(!hasXl));   // edge lanes, interior z
    const float missE3 = (float)(missY + (int)(!hasXr));
    const float missM  = (float)missY;

    float4 A = (z0 > 0) ? *(const float4*)(p - plane) : zero4;  // z-1
    float4 B = *(const float4*)(p);                              // z

    #pragma unroll
    for (int iz = 0; iz < KZ; ++iz) {
        const int z = z0 + iz;
        float4 C = (z < DSZ - 1) ? *(const float4*)(p + plane) : zero4;  // z+1
        float4 ym = hasYm ? *(const float4*)(p - DSZ) : zero4;
        float4 yp = hasYp ? *(const float4*)(p + DSZ) : zero4;
        float  xl = hasXl ? __ldg(p - 1) : 0.f;
        float  xr = hasXr ? __ldg(p + 4) : 0.f;

        float L0 = 6.f * B.x - (xl  + B.y + ym.x + yp.x + A.x + C.x);
        float L1 = 6.f * B.y - (B.x + B.z + ym.y + yp.y + A.y + C.y);
        float L2 = 6.f * B.z - (B.y + B.w + ym.z + yp.z + A.z + C.z);
        float L3 = 6.f * B.w - (B.z + xr  + ym.w + yp.w + A.w + C.w);

        const float mz = (float)((int)(z == 0) + (int)(z == DSZ - 1));
        const float f0 = missE0 + mz;
        const float fm = missM  + mz;
        const float f3 = missE3 + mz;

        float4 o;
        o.x = ((L0 >= 0.f) || (f0 - L0 >= 0.5f)) ? 1.f : 0.f;
        o.y = ((L1 >= 0.f) || (fm - L1 >= 0.5f)) ? 1.f : 0.f;
        o.z = ((L2 >= 0.f) || (fm - L2 >= 0.5f)) ? 1.f : 0.f;
        o.w = ((L3 >= 0.f) || (f3 - L3 >= 0.5f)) ? 1.f : 0.f;

        *(float4*)(q) = o;

        A = B; B = C;
        p += plane; q += plane;
    }
}

extern "C" void kernel_launch(void* const* d_in, const int* in_sizes, int n_in,
                              void* d_out, int out_size)
{
    const float* m = (const float*)d_in[0];
    float* out = (float*)d_out;

    dim3 block(48, 8, 1);                       // 384 threads: full row x 8 rows
    dim3 grid(1, DSZ / 8, 2 * (DSZ / KZ));      // y-tiles, (batch * z-tiles)
    mask_kernel<<<grid, block>>>(m, out);
}

// round 4
// speedup vs baseline: 1.1028x; 1.1028x over previous
#include <cuda_runtime.h>
#include <cstdint>

// out[p] = (L >= 0) || (missing(p) - L >= 0.5), written as float 0.0/1.0
// L = 7-point Laplacian (6*center - face neighbors, zero padding);
// missing(p) = count of out-of-grid face neighbors (kernel sums to 0, so
// conv(1-m,k) = missing(p) - conv(m,k)).
//
// Each thread: one x-quad (float4) of one y-row, rolling over KZ z-slices.
// KZ=6 + launch_bounds(384,5): keep regs <=34 so 5 CTAs/SM (60 warps) fit.

#define DSZ 192
#define KZ  6
#define ZT  (DSZ / KZ)   // 32 z-tiles

__global__ __launch_bounds__(384, 5) void mask_kernel(
    const float* __restrict__ m, float* __restrict__ out)
{
    const int tx = threadIdx.x;                       // 0..47 -> x quad
    const int y  = blockIdx.y * blockDim.y + threadIdx.y;
    const int zb = blockIdx.z;
    const int z0 = (zb & (ZT - 1)) * KZ;
    const int b  = zb / ZT;
    const int x0 = tx * 4;

    const size_t plane = (size_t)DSZ * DSZ;
    const float* p = m + (((size_t)b * DSZ + z0) * DSZ + y) * DSZ + x0;
    float* q = out + (((size_t)b * DSZ + z0) * DSZ + y) * DSZ + x0;

    const float4 zero4 = make_float4(0.f, 0.f, 0.f, 0.f);
    const bool hasYm = (y > 0);
    const bool hasYp = (y < DSZ - 1);
    const bool hasXl = (x0 > 0);
    const bool hasXr = (x0 + 4 < DSZ);
    const int  missY = (int)(!hasYm) + (int)(!hasYp);
    const float missE0 = (float)(missY + (int)(!hasXl));
    const float missE3 = (float)(missY + (int)(!hasXr));
    const float missM  = (float)missY;

    float4 A = (z0 > 0) ? *(const float4*)(p - plane) : zero4;  // z-1
    float4 B = *(const float4*)(p);                              // z

    #pragma unroll
    for (int iz = 0; iz < KZ; ++iz) {
        const int z = z0 + iz;
        float4 C = (z < DSZ - 1) ? *(const float4*)(p + plane) : zero4;  // z+1
        float4 ym = hasYm ? *(const float4*)(p - DSZ) : zero4;
        float4 yp = hasYp ? *(const float4*)(p + DSZ) : zero4;
        float  xl = hasXl ? __ldg(p - 1) : 0.f;
        float  xr = hasXr ? __ldg(p + 4) : 0.f;

        float L0 = 6.f * B.x - (xl  + B.y + ym.x + yp.x + A.x + C.x);
        float L1 = 6.f * B.y - (B.x + B.z + ym.y + yp.y + A.y + C.y);
        float L2 = 6.f * B.z - (B.y + B.w + ym.z + yp.z + A.z + C.z);
        float L3 = 6.f * B.w - (B.z + xr  + ym.w + yp.w + A.w + C.w);

        const float mz = (float)((int)(z == 0) + (int)(z == DSZ - 1));
        const float f0 = missE0 + mz;
        const float fm = missM  + mz;
        const float f3 = missE3 + mz;

        float4 o;
        o.x = ((L0 >= 0.f) || (f0 - L0 >= 0.5f)) ? 1.f : 0.f;
        o.y = ((L1 >= 0.f) || (fm - L1 >= 0.5f)) ? 1.f : 0.f;
        o.z = ((L2 >= 0.f) || (fm - L2 >= 0.5f)) ? 1.f : 0.f;
        o.w = ((L3 >= 0.f) || (f3 - L3 >= 0.5f)) ? 1.f : 0.f;

        *(float4*)(q) = o;

        A = B; B = C;
        p += plane; q += plane;
    }
}

extern "C" void kernel_launch(void* const* d_in, const int* in_sizes, int n_in,
                              void* d_out, int out_size)
{
    const float* m = (const float*)d_in[0];
    float* out = (float*)d_out;

    dim3 block(48, 8, 1);                 // 384 threads: full row x 8 rows
    dim3 grid(1, DSZ / 8, 2 * ZT);        // y-tiles, (batch * z-tiles)
    mask_kernel<<<grid, block>>>(m, out);
}